// round 1
// baseline (speedup 1.0000x reference)
#include <cuda_runtime.h>

// Problem constants
#define DD   1024
#define NB   8
#define TQ   1024
#define MT   (NB*TQ)        // 8192 rows when batch folded into M
#define OUTC 6144           // output inner dim: 6 x 1024

// Scratch: 15 slots of 8192*1024 floats each (~503 MB static, allocation-free)
// slots: fp1..3 -> 0..2, q1..3 -> 3..5, k1..3 -> 6..8, v1..3 -> 9..11,
//        qs1 -> 12, qs3 -> 13, S -> 14
#define SLOT 8388608ULL
__device__ float g_scratch[15ULL * SLOT];

// ---------------------------------------------------------------------------
// SGEMM: C[M,N] = A[M,K] * op(B) (+ C) (+bias, relu)
//   BT=true : B is [N,K] row-major (op(B)=B^T), i.e. einsum 'mk,nk->mn'
//   BT=false: B is [K,N] row-major,              i.e. einsum 'mk,kn->mn'
// 128x128 tile, BK=8, 256 threads, 8x8 per thread. M,N,K multiples of 128/8.
// Optional second output C2 (same values, own leading dim) for fused fp->out.
// ---------------------------------------------------------------------------
template<bool BT, bool BIASRELU, bool ACC>
__global__ void __launch_bounds__(256)
sgemm_k(const float* __restrict__ A, int lda, size_t sA,
        const float* __restrict__ B, int ldb, size_t sB,
        const float* __restrict__ bias,
        float* __restrict__ C, int ldc, size_t sC,
        float* __restrict__ C2, int ldc2,
        int K)
{
    __shared__ float As[8][128];
    __shared__ float Bs[8][128];

    const int tid = threadIdx.x;
    const int tx  = tid & 15;          // 0..15  -> 8 cols each
    const int ty  = tid >> 4;          // 0..15  -> 8 rows each
    const size_t rowBase = (size_t)blockIdx.y * 128;
    const size_t colBase = (size_t)blockIdx.x * 128;

    const float* Ab = A + (size_t)blockIdx.z * sA;
    const float* Bb = B + (size_t)blockIdx.z * sB;
    float*       Cb = C + (size_t)blockIdx.z * sC;

    const int lrow = tid >> 1;          // 0..127
    const int lk   = (tid & 1) * 4;     // 0 or 4
    const int bk   = tid >> 5;          // 0..7   (NN B load)
    const int bn   = (tid & 31) * 4;    // 0..124

    float acc[8][8];
#pragma unroll
    for (int i = 0; i < 8; i++)
#pragma unroll
        for (int j = 0; j < 8; j++) acc[i][j] = 0.f;

    for (int k0 = 0; k0 < K; k0 += 8) {
        float4 av = *(const float4*)(Ab + (rowBase + lrow) * (size_t)lda + k0 + lk);
        As[lk + 0][lrow] = av.x; As[lk + 1][lrow] = av.y;
        As[lk + 2][lrow] = av.z; As[lk + 3][lrow] = av.w;
        if (BT) {
            float4 bv = *(const float4*)(Bb + (colBase + lrow) * (size_t)ldb + k0 + lk);
            Bs[lk + 0][lrow] = bv.x; Bs[lk + 1][lrow] = bv.y;
            Bs[lk + 2][lrow] = bv.z; Bs[lk + 3][lrow] = bv.w;
        } else {
            float4 bv = *(const float4*)(Bb + (size_t)(k0 + bk) * (size_t)ldb + colBase + bn);
            *(float4*)&Bs[bk][bn] = bv;
        }
        __syncthreads();

#pragma unroll
        for (int kk = 0; kk < 8; kk++) {
            float a[8], b[8];
            *(float4*)(a)     = *(const float4*)&As[kk][ty * 8];
            *(float4*)(a + 4) = *(const float4*)&As[kk][ty * 8 + 4];
            *(float4*)(b)     = *(const float4*)&Bs[kk][tx * 8];
            *(float4*)(b + 4) = *(const float4*)&Bs[kk][tx * 8 + 4];
#pragma unroll
            for (int i = 0; i < 8; i++)
#pragma unroll
                for (int j = 0; j < 8; j++)
                    acc[i][j] = fmaf(a[i], b[j], acc[i][j]);
        }
        __syncthreads();
    }

#pragma unroll
    for (int i = 0; i < 8; i++) {
        size_t r = rowBase + ty * 8 + i;
#pragma unroll
        for (int j = 0; j < 8; j += 4) {
            size_t c = colBase + tx * 8 + j;
            float4 v = make_float4(acc[i][j], acc[i][j + 1], acc[i][j + 2], acc[i][j + 3]);
            if (ACC) {
                float4 o = *(const float4*)(Cb + r * (size_t)ldc + c);
                v.x += o.x; v.y += o.y; v.z += o.z; v.w += o.w;
            }
            if (BIASRELU) {
                v.x = fmaxf(v.x + bias[c + 0], 0.f);
                v.y = fmaxf(v.y + bias[c + 1], 0.f);
                v.z = fmaxf(v.z + bias[c + 2], 0.f);
                v.w = fmaxf(v.w + bias[c + 3], 0.f);
            }
            *(float4*)(Cb + r * (size_t)ldc + c) = v;
            if (C2) *(float4*)(C2 + r * (size_t)ldc2 + c) = v;
        }
    }
}

// o = a + b (float4 granularity)
__global__ void add_k(const float* __restrict__ a, const float* __restrict__ b,
                      float* __restrict__ o, int n4)
{
    int i = blockIdx.x * blockDim.x + threadIdx.x;
    if (i < n4) {
        float4 x = ((const float4*)a)[i];
        float4 y = ((const float4*)b)[i];
        x.x += y.x; x.y += y.y; x.z += y.z; x.w += y.w;
        ((float4*)o)[i] = x;
    }
}

// In-place row softmax over rows of length 1024. One block (256 thr) per row.
__global__ void softmax_k(float* __restrict__ S)
{
    __shared__ float red[256];
    float* p = S + (size_t)blockIdx.x * 1024;
    int tid = threadIdx.x;

    float4 v = *(float4*)&p[tid * 4];
    float m = fmaxf(fmaxf(v.x, v.y), fmaxf(v.z, v.w));
    red[tid] = m; __syncthreads();
    for (int s = 128; s > 0; s >>= 1) {
        if (tid < s) red[tid] = fmaxf(red[tid], red[tid + s]);
        __syncthreads();
    }
    m = red[0]; __syncthreads();

    v.x = __expf(v.x - m); v.y = __expf(v.y - m);
    v.z = __expf(v.z - m); v.w = __expf(v.w - m);
    float s = v.x + v.y + v.z + v.w;
    red[tid] = s; __syncthreads();
    for (int t = 128; t > 0; t >>= 1) {
        if (tid < t) red[tid] += red[tid + t];
        __syncthreads();
    }
    float inv = 1.f / red[0];
    v.x *= inv; v.y *= inv; v.z *= inv; v.w *= inv;
    *(float4*)&p[tid * 4] = v;
}

extern "C" void kernel_launch(void* const* d_in, const int* in_sizes, int n_in,
                              void* d_out, int out_size)
{
    // metadata order: f1,f2,f3, Wp1,Wp2,Wp3, Wq1,Wk1,Wv1, Wq2,Wk2,Wv2, Wq3,Wk3,Wv3, bp1,bp2,bp3
    const float* f[3]  = { (const float*)d_in[0],  (const float*)d_in[1],  (const float*)d_in[2]  };
    const float* Wp[3] = { (const float*)d_in[3],  (const float*)d_in[4],  (const float*)d_in[5]  };
    const float* Wq[3] = { (const float*)d_in[6],  (const float*)d_in[9],  (const float*)d_in[12] };
    const float* Wk[3] = { (const float*)d_in[7],  (const float*)d_in[10], (const float*)d_in[13] };
    const float* Wv[3] = { (const float*)d_in[8],  (const float*)d_in[11], (const float*)d_in[14] };
    const float* bp[3] = { (const float*)d_in[15], (const float*)d_in[16], (const float*)d_in[17] };
    float* out = (float*)d_out;

    float* base = nullptr;
    cudaGetSymbolAddress((void**)&base, g_scratch);
    float *fp[3], *q[3], *kk[3], *vv[3];
    for (int i = 0; i < 3; i++) {
        fp[i] = base + (0 + i) * SLOT;
        q[i]  = base + (3 + i) * SLOT;
        kk[i] = base + (6 + i) * SLOT;
        vv[i] = base + (9 + i) * SLOT;
    }
    float* qs1 = base + 12 * SLOT;   // q2+q3
    float* qs3 = base + 13 * SLOT;   // q1+q2
    float* S   = base + 14 * SLOT;   // score scratch (reused per modality)

    dim3 blk(256);
    dim3 gFull(DD / 128, MT / 128, 1);   // (8, 64)
    dim3 gBat(TQ / 128, TQ / 128, NB);   // (8, 8, 8)

    // 1) preprocess: fp_i = relu(f_i @ Wp_i^T + bp_i); also write to out cols [3072 + i*1024)
    for (int i = 0; i < 3; i++)
        sgemm_k<true, true, false><<<gFull, blk>>>(
            f[i], DD, 0, Wp[i], DD, 0, bp[i],
            fp[i], DD, 0, out + 3072 + i * 1024, OUTC, DD);

    // 2) QKV projections
    for (int i = 0; i < 3; i++) {
        sgemm_k<true, false, false><<<gFull, blk>>>(fp[i], DD, 0, Wq[i], DD, 0, nullptr, q[i],  DD, 0, nullptr, 0, DD);
        sgemm_k<true, false, false><<<gFull, blk>>>(fp[i], DD, 0, Wk[i], DD, 0, nullptr, kk[i], DD, 0, nullptr, 0, DD);
        sgemm_k<true, false, false><<<gFull, blk>>>(fp[i], DD, 0, Wv[i], DD, 0, nullptr, vv[i], DD, 0, nullptr, 0, DD);
    }

    // 3) combined queries: s1 = (q2+q3) k1^T ; s3 = (q1+q2) k3^T
    int n4 = MT * DD / 4;
    add_k<<<(n4 + 255) / 256, 256>>>(q[1], q[2], qs1, n4);
    add_k<<<(n4 + 255) / 256, 256>>>(q[0], q[1], qs3, n4);

    const size_t SB = (size_t)TQ * DD;     // per-batch stride for Q/K/V/S
    const size_t SO = (size_t)TQ * OUTC;   // per-batch stride in output

    // modality 1: s1 = qs1 . k1^T ; f1u = softmax(s1) @ v1 -> out cols [0,1024)
    sgemm_k<true,  false, false><<<gBat, blk>>>(qs1, DD, SB, kk[0], DD, SB, nullptr, S, TQ, SB, nullptr, 0, DD);
    softmax_k<<<MT, 256>>>(S);
    sgemm_k<false, false, false><<<gBat, blk>>>(S, TQ, SB, vv[0], DD, SB, nullptr, out + 0, OUTC, SO, nullptr, 0, TQ);

    // modality 2: s2 = q1.k3^T + q3.k2^T ; f2u -> out cols [1024,2048)
    sgemm_k<true,  false, false><<<gBat, blk>>>(q[0], DD, SB, kk[2], DD, SB, nullptr, S, TQ, SB, nullptr, 0, DD);
    sgemm_k<true,  false, true ><<<gBat, blk>>>(q[2], DD, SB, kk[1], DD, SB, nullptr, S, TQ, SB, nullptr, 0, DD);
    softmax_k<<<MT, 256>>>(S);
    sgemm_k<false, false, false><<<gBat, blk>>>(S, TQ, SB, vv[1], DD, SB, nullptr, out + 1024, OUTC, SO, nullptr, 0, TQ);

    // modality 3: s3 = qs3 . k3^T ; f3u -> out cols [2048,3072)
    sgemm_k<true,  false, false><<<gBat, blk>>>(qs3, DD, SB, kk[2], DD, SB, nullptr, S, TQ, SB, nullptr, 0, DD);
    softmax_k<<<MT, 256>>>(S);
    sgemm_k<false, false, false><<<gBat, blk>>>(S, TQ, SB, vv[2], DD, SB, nullptr, out + 2048, OUTC, SO, nullptr, 0, TQ);
}

// round 2
// speedup vs baseline: 1.0002x; 1.0002x over previous
#include <cuda_runtime.h>

// Problem constants
#define DD   1024
#define NB   8
#define TQ   1024
#define MT   (NB*TQ)        // 8192 rows when batch folded into M
#define OUTC 6144           // output inner dim: 6 x 1024

// Scratch: 15 slots of 8192*1024 floats each (~503 MB static, allocation-free)
// slots: fp1..3 -> 0..2, q1..3 -> 3..5, k1..3 -> 6..8, v1..3 -> 9..11,
//        qs1 -> 12, qs3 -> 13, S -> 14
#define SLOT 8388608ULL
__device__ float g_scratch[15ULL * SLOT];

// ---------------------------------------------------------------------------
// SGEMM: C[M,N] = A[M,K] * op(B) (+ C) (+bias, relu)
//   BT=true : B is [N,K] row-major (op(B)=B^T), i.e. einsum 'mk,nk->mn'
//   BT=false: B is [K,N] row-major,              i.e. einsum 'mk,kn->mn'
// 128x128 tile, BK=8, 256 threads, 8x8 per thread. M,N,K multiples of 128/8.
// Optional second output C2 (same values, own leading dim) for fused fp->out.
// ---------------------------------------------------------------------------
template<bool BT, bool BIASRELU, bool ACC>
__global__ void __launch_bounds__(256)
sgemm_k(const float* __restrict__ A, int lda, size_t sA,
        const float* __restrict__ B, int ldb, size_t sB,
        const float* __restrict__ bias,
        float* __restrict__ C, int ldc, size_t sC,
        float* __restrict__ C2, int ldc2,
        int K)
{
    __shared__ float As[8][128];
    __shared__ float Bs[8][128];

    const int tid = threadIdx.x;
    const int tx  = tid & 15;          // 0..15  -> 8 cols each
    const int ty  = tid >> 4;          // 0..15  -> 8 rows each
    const size_t rowBase = (size_t)blockIdx.y * 128;
    const size_t colBase = (size_t)blockIdx.x * 128;

    const float* Ab = A + (size_t)blockIdx.z * sA;
    const float* Bb = B + (size_t)blockIdx.z * sB;
    float*       Cb = C + (size_t)blockIdx.z * sC;

    const int lrow = tid >> 1;          // 0..127
    const int lk   = (tid & 1) * 4;     // 0 or 4
    const int bk   = tid >> 5;          // 0..7   (NN B load)
    const int bn   = (tid & 31) * 4;    // 0..124

    float acc[8][8];
#pragma unroll
    for (int i = 0; i < 8; i++)
#pragma unroll
        for (int j = 0; j < 8; j++) acc[i][j] = 0.f;

    for (int k0 = 0; k0 < K; k0 += 8) {
        float4 av = *(const float4*)(Ab + (rowBase + lrow) * (size_t)lda + k0 + lk);
        As[lk + 0][lrow] = av.x; As[lk + 1][lrow] = av.y;
        As[lk + 2][lrow] = av.z; As[lk + 3][lrow] = av.w;
        if (BT) {
            float4 bv = *(const float4*)(Bb + (colBase + lrow) * (size_t)ldb + k0 + lk);
            Bs[lk + 0][lrow] = bv.x; Bs[lk + 1][lrow] = bv.y;
            Bs[lk + 2][lrow] = bv.z; Bs[lk + 3][lrow] = bv.w;
        } else {
            float4 bv = *(const float4*)(Bb + (size_t)(k0 + bk) * (size_t)ldb + colBase + bn);
            *(float4*)&Bs[bk][bn] = bv;
        }
        __syncthreads();

#pragma unroll
        for (int kk = 0; kk < 8; kk++) {
            float a[8], b[8];
            *(float4*)(a)     = *(const float4*)&As[kk][ty * 8];
            *(float4*)(a + 4) = *(const float4*)&As[kk][ty * 8 + 4];
            *(float4*)(b)     = *(const float4*)&Bs[kk][tx * 8];
            *(float4*)(b + 4) = *(const float4*)&Bs[kk][tx * 8 + 4];
#pragma unroll
            for (int i = 0; i < 8; i++)
#pragma unroll
                for (int j = 0; j < 8; j++)
                    acc[i][j] = fmaf(a[i], b[j], acc[i][j]);
        }
        __syncthreads();
    }

#pragma unroll
    for (int i = 0; i < 8; i++) {
        size_t r = rowBase + ty * 8 + i;
#pragma unroll
        for (int j = 0; j < 8; j += 4) {
            size_t c = colBase + tx * 8 + j;
            float4 v = make_float4(acc[i][j], acc[i][j + 1], acc[i][j + 2], acc[i][j + 3]);
            if (ACC) {
                float4 o = *(const float4*)(Cb + r * (size_t)ldc + c);
                v.x += o.x; v.y += o.y; v.z += o.z; v.w += o.w;
            }
            if (BIASRELU) {
                v.x = fmaxf(v.x + bias[c + 0], 0.f);
                v.y = fmaxf(v.y + bias[c + 1], 0.f);
                v.z = fmaxf(v.z + bias[c + 2], 0.f);
                v.w = fmaxf(v.w + bias[c + 3], 0.f);
            }
            *(float4*)(Cb + r * (size_t)ldc + c) = v;
            if (C2) *(float4*)(C2 + r * (size_t)ldc2 + c) = v;
        }
    }
}

// o = a + b (float4 granularity)
__global__ void add_k(const float* __restrict__ a, const float* __restrict__ b,
                      float* __restrict__ o, int n4)
{
    int i = blockIdx.x * blockDim.x + threadIdx.x;
    if (i < n4) {
        float4 x = ((const float4*)a)[i];
        float4 y = ((const float4*)b)[i];
        x.x += y.x; x.y += y.y; x.z += y.z; x.w += y.w;
        ((float4*)o)[i] = x;
    }
}

// In-place row softmax over rows of length 1024. One block (256 thr) per row.
__global__ void softmax_k(float* __restrict__ S)
{
    __shared__ float red[256];
    float* p = S + (size_t)blockIdx.x * 1024;
    int tid = threadIdx.x;

    float4 v = *(float4*)&p[tid * 4];
    float m = fmaxf(fmaxf(v.x, v.y), fmaxf(v.z, v.w));
    red[tid] = m; __syncthreads();
    for (int s = 128; s > 0; s >>= 1) {
        if (tid < s) red[tid] = fmaxf(red[tid], red[tid + s]);
        __syncthreads();
    }
    m = red[0]; __syncthreads();

    v.x = __expf(v.x - m); v.y = __expf(v.y - m);
    v.z = __expf(v.z - m); v.w = __expf(v.w - m);
    float s = v.x + v.y + v.z + v.w;
    red[tid] = s; __syncthreads();
    for (int t = 128; t > 0; t >>= 1) {
        if (tid < t) red[tid] += red[tid + t];
        __syncthreads();
    }
    float inv = 1.f / red[0];
    v.x *= inv; v.y *= inv; v.z *= inv; v.w *= inv;
    *(float4*)&p[tid * 4] = v;
}

extern "C" void kernel_launch(void* const* d_in, const int* in_sizes, int n_in,
                              void* d_out, int out_size)
{
    // metadata order: f1,f2,f3, Wp1,Wp2,Wp3, Wq1,Wk1,Wv1, Wq2,Wk2,Wv2, Wq3,Wk3,Wv3, bp1,bp2,bp3
    const float* f[3]  = { (const float*)d_in[0],  (const float*)d_in[1],  (const float*)d_in[2]  };
    const float* Wp[3] = { (const float*)d_in[3],  (const float*)d_in[4],  (const float*)d_in[5]  };
    const float* Wq[3] = { (const float*)d_in[6],  (const float*)d_in[9],  (const float*)d_in[12] };
    const float* Wk[3] = { (const float*)d_in[7],  (const float*)d_in[10], (const float*)d_in[13] };
    const float* Wv[3] = { (const float*)d_in[8],  (const float*)d_in[11], (const float*)d_in[14] };
    const float* bp[3] = { (const float*)d_in[15], (const float*)d_in[16], (const float*)d_in[17] };
    float* out = (float*)d_out;

    float* base = nullptr;
    cudaGetSymbolAddress((void**)&base, g_scratch);
    float *fp[3], *q[3], *kk[3], *vv[3];
    for (int i = 0; i < 3; i++) {
        fp[i] = base + (0 + i) * SLOT;
        q[i]  = base + (3 + i) * SLOT;
        kk[i] = base + (6 + i) * SLOT;
        vv[i] = base + (9 + i) * SLOT;
    }
    float* qs1 = base + 12 * SLOT;   // q2+q3
    float* qs3 = base + 13 * SLOT;   // q1+q2
    float* S   = base + 14 * SLOT;   // score scratch (reused per modality)

    dim3 blk(256);
    dim3 gFull(DD / 128, MT / 128, 1);   // (8, 64)
    dim3 gBat(TQ / 128, TQ / 128, NB);   // (8, 8, 8)

    // 1) preprocess: fp_i = relu(f_i @ Wp_i^T + bp_i); also write to out cols [3072 + i*1024)
    for (int i = 0; i < 3; i++)
        sgemm_k<true, true, false><<<gFull, blk>>>(
            f[i], DD, 0, Wp[i], DD, 0, bp[i],
            fp[i], DD, 0, out + 3072 + i * 1024, OUTC, DD);

    // 2) QKV projections
    for (int i = 0; i < 3; i++) {
        sgemm_k<true, false, false><<<gFull, blk>>>(fp[i], DD, 0, Wq[i], DD, 0, nullptr, q[i],  DD, 0, nullptr, 0, DD);
        sgemm_k<true, false, false><<<gFull, blk>>>(fp[i], DD, 0, Wk[i], DD, 0, nullptr, kk[i], DD, 0, nullptr, 0, DD);
        sgemm_k<true, false, false><<<gFull, blk>>>(fp[i], DD, 0, Wv[i], DD, 0, nullptr, vv[i], DD, 0, nullptr, 0, DD);
    }

    // 3) combined queries: s1 = (q2+q3) k1^T ; s3 = (q1+q2) k3^T
    int n4 = MT * DD / 4;
    add_k<<<(n4 + 255) / 256, 256>>>(q[1], q[2], qs1, n4);
    add_k<<<(n4 + 255) / 256, 256>>>(q[0], q[1], qs3, n4);

    const size_t SB = (size_t)TQ * DD;     // per-batch stride for Q/K/V/S
    const size_t SO = (size_t)TQ * OUTC;   // per-batch stride in output

    // modality 1: s1 = qs1 . k1^T ; f1u = softmax(s1) @ v1 -> out cols [0,1024)
    sgemm_k<true,  false, false><<<gBat, blk>>>(qs1, DD, SB, kk[0], DD, SB, nullptr, S, TQ, SB, nullptr, 0, DD);
    softmax_k<<<MT, 256>>>(S);
    sgemm_k<false, false, false><<<gBat, blk>>>(S, TQ, SB, vv[0], DD, SB, nullptr, out + 0, OUTC, SO, nullptr, 0, TQ);

    // modality 2: s2 = q1.k3^T + q3.k2^T ; f2u -> out cols [1024,2048)
    sgemm_k<true,  false, false><<<gBat, blk>>>(q[0], DD, SB, kk[2], DD, SB, nullptr, S, TQ, SB, nullptr, 0, DD);
    sgemm_k<true,  false, true ><<<gBat, blk>>>(q[2], DD, SB, kk[1], DD, SB, nullptr, S, TQ, SB, nullptr, 0, DD);
    softmax_k<<<MT, 256>>>(S);
    sgemm_k<false, false, false><<<gBat, blk>>>(S, TQ, SB, vv[1], DD, SB, nullptr, out + 1024, OUTC, SO, nullptr, 0, TQ);

    // modality 3: s3 = qs3 . k3^T ; f3u -> out cols [2048,3072)
    sgemm_k<true,  false, false><<<gBat, blk>>>(qs3, DD, SB, kk[2], DD, SB, nullptr, S, TQ, SB, nullptr, 0, DD);
    softmax_k<<<MT, 256>>>(S);
    sgemm_k<false, false, false><<<gBat, blk>>>(S, TQ, SB, vv[2], DD, SB, nullptr, out + 2048, OUTC, SO, nullptr, 0, TQ);
}

// round 4
// speedup vs baseline: 2.7967x; 2.7961x over previous
#include <cuda_runtime.h>
#include <cuda_bf16.h>
#include <cstdint>

typedef __nv_bfloat16 bf16;

#define BM 128
#define BN 128
#define STAGES 3
#define STAGE_BYTES 32768               // A 128x128B + B 128x128B
#define SMEM_ALLOC (1024 + STAGES*STAGE_BYTES)

#define BIG 8388608ULL
#define MB1 1048576ULL
#define OFF_FP  (6ULL*BIG)
#define OFF_Q   (12ULL*BIG)
#define OFF_K   (18ULL*BIG)
#define OFF_VT  (24ULL*BIG)
#define OFF_P   (30ULL*BIG)
#define OFF_W   (32ULL*BIG)

__device__ bf16  g_bf[32ULL*BIG + 24ULL*MB1];
__device__ float g_S[BIG];

__device__ __forceinline__ uint32_t su32(const void* p){ return (uint32_t)__cvta_generic_to_shared(p); }
__device__ __forceinline__ void cp16(uint32_t s, const void* g){
    asm volatile("cp.async.cg.shared.global [%0], [%1], 16;"
        :: "r"(s), "l"((unsigned long long)__cvta_generic_to_global(g)) : "memory");
}
__device__ __forceinline__ uint32_t pk(bf16 a, bf16 b){
    return (uint32_t)__bfloat16_as_ushort(a) | ((uint32_t)__bfloat16_as_ushort(b) << 16);
}
__device__ __forceinline__ uint32_t swz(uint32_t o){ return o ^ ((o >> 3) & 0x70); }

__device__ __forceinline__ void ldsm4(uint32_t* r, uint32_t addr){
    asm volatile("ldmatrix.sync.aligned.m8n8.x4.shared.b16 {%0,%1,%2,%3}, [%4];"
        : "=r"(r[0]), "=r"(r[1]), "=r"(r[2]), "=r"(r[3]) : "r"(addr));
}
__device__ __forceinline__ void mma16816(float* d, const uint32_t* a, const uint32_t* b){
    asm volatile("mma.sync.aligned.m16n8k16.row.col.f32.bf16.bf16.f32 "
        "{%0,%1,%2,%3}, {%4,%5,%6,%7}, {%8,%9}, {%0,%1,%2,%3};"
        : "+f"(d[0]), "+f"(d[1]), "+f"(d[2]), "+f"(d[3])
        : "r"(a[0]), "r"(a[1]), "r"(a[2]), "r"(a[3]), "r"(b[0]), "r"(b[1]));
}

struct GArgs {
    const bf16 *Ah[2], *Al[2], *Bh[2], *Bl[2];
    int npairs;
    long long sA, sB;
    const float* bias;
    float* Cf; int ldcf; long long sCf;
    bf16 *Chi, *Clo;
};

// C[M,N] = sum over pairs of (Ah Bh^T + Al Bh^T + Ah Bl^T); rows K=1024-contig
template<bool BIASRELU, bool WF32, bool WSPLIT, bool WTRANS>
__global__ void __launch_bounds__(256)
gemm_mma(GArgs g)
{
    extern __shared__ char smem[];
    const uint32_t tbase = (su32(smem) + 1023u) & ~1023u;
    const int tid = threadIdx.x, wid = tid >> 5, lane = tid & 31;
    const int m0 = blockIdx.y * BM, n0 = blockIdx.x * BN;
    const long long zo = blockIdx.z;
    const int wm = (wid & 3) * 32, wn = (wid >> 2) * 64;

    const bf16 *sgA[6], *sgB[6];
    for (int p = 0; p < g.npairs; p++) {
        const bf16* AH = g.Ah[p] + zo * g.sA;
        const bf16* AL = g.Al[p] + zo * g.sA;
        const bf16* BH = g.Bh[p] + zo * g.sB;
        const bf16* BL = g.Bl[p] + zo * g.sB;
        sgA[3*p+0] = AH; sgB[3*p+0] = BH;
        sgA[3*p+1] = AL; sgB[3*p+1] = BH;
        sgA[3*p+2] = AH; sgB[3*p+2] = BL;
    }
    const int nch = g.npairs * 48;      // 3 segs * 16 chunks (K=64 each)

    float acc[2][8][4];
#pragma unroll
    for (int a = 0; a < 2; a++)
#pragma unroll
        for (int b = 0; b < 8; b++)
#pragma unroll
            for (int c = 0; c < 4; c++) acc[a][b][c] = 0.f;

    auto load_chunk = [&](int j, int slot) {
        const int seg = j >> 4;
        const int k0  = (j & 15) * 64;
        const bf16* Ap = sgA[seg];
        const bf16* Bp = sgB[seg];
        const uint32_t sa = tbase + slot * STAGE_BYTES;
        const uint32_t sb = sa + 16384;
#pragma unroll
        for (int u = 0; u < 4; u++) {
            int s = tid + 256 * u;         // 0..1023
            int row = s >> 3, cs = s & 7;
            uint32_t so = swz((uint32_t)(row * 128 + cs * 16));
            cp16(sa + so, Ap + (size_t)(m0 + row) * 1024 + k0 + cs * 8);
            cp16(sb + so, Bp + (size_t)(n0 + row) * 1024 + k0 + cs * 8);
        }
        asm volatile("cp.async.commit_group;" ::: "memory");
    };

    load_chunk(0, 0);
    load_chunk(1, 1);

    const int r8 = lane & 7, sg = lane >> 3;

    for (int i = 0; i < nch; i++) {
        const int j = i + 2;
        if (j < nch) {
            load_chunk(j, j % STAGES);
            asm volatile("cp.async.wait_group 2;" ::: "memory");
        } else {
            asm volatile("cp.async.wait_group 0;" ::: "memory");
        }
        __syncthreads();

        const uint32_t sa = tbase + (i % STAGES) * STAGE_BYTES;
        const uint32_t sb = sa + 16384;
#pragma unroll
        for (int ks = 0; ks < 4; ks++) {
            const int kb = ks * 32;                      // bytes
            uint32_t af[2][4];
#pragma unroll
            for (int mt = 0; mt < 2; mt++) {
                int row = wm + mt * 16 + r8 + ((sg & 1) << 3);
                ldsm4(af[mt], sa + swz((uint32_t)(row * 128 + kb + ((sg >> 1) << 4))));
            }
            uint32_t bfr[4][4];
#pragma unroll
            for (int nq = 0; nq < 4; nq++) {
                int row = wn + nq * 16 + r8 + ((sg >> 1) << 3);
                ldsm4(bfr[nq], sb + swz((uint32_t)(row * 128 + kb + ((sg & 1) << 4))));
            }
#pragma unroll
            for (int mt = 0; mt < 2; mt++)
#pragma unroll
                for (int nq = 0; nq < 4; nq++) {
                    mma16816(acc[mt][2*nq],     af[mt], bfr[nq]);
                    mma16816(acc[mt][2*nq + 1], af[mt], bfr[nq] + 2);
                }
        }
        __syncthreads();
    }

    // epilogue: d-frag regs {0,1}=row lane/4, {2,3}=row+8; cols (lane&3)*2, +1
#pragma unroll
    for (int mt = 0; mt < 2; mt++)
#pragma unroll
        for (int ri = 0; ri < 2; ri++) {
            const long long rg = m0 + wm + mt * 16 + ri * 8 + (lane >> 2);
            float* cf = WF32 ? (g.Cf + zo * g.sCf + rg * (long long)g.ldcf) : nullptr;
            bf16 *chi = nullptr, *clo = nullptr;
            long long bb = 0, tb = 0;
            if (WSPLIT) {
                if (WTRANS) { bb = (rg >> 10) * 1048576LL; tb = rg & 1023LL; }
                else        { chi = g.Chi + rg * 1024LL; clo = g.Clo + rg * 1024LL; }
            }
#pragma unroll
            for (int nt = 0; nt < 8; nt++) {
                const int c = n0 + wn + nt * 8 + (lane & 3) * 2;
                float v0 = acc[mt][nt][ri * 2];
                float v1 = acc[mt][nt][ri * 2 + 1];
                if (BIASRELU) {
                    v0 = fmaxf(v0 + g.bias[c], 0.f);
                    v1 = fmaxf(v1 + g.bias[c + 1], 0.f);
                }
                if (WF32) *(float2*)(cf + c) = make_float2(v0, v1);
                if (WSPLIT) {
                    bf16 h0 = __float2bfloat16(v0), h1 = __float2bfloat16(v1);
                    bf16 l0 = __float2bfloat16(v0 - __bfloat162float(h0));
                    bf16 l1 = __float2bfloat16(v1 - __bfloat162float(h1));
                    if (WTRANS) {
                        g.Chi[bb + (long long)c * 1024 + tb] = h0;
                        g.Chi[bb + (long long)(c + 1) * 1024 + tb] = h1;
                        g.Clo[bb + (long long)c * 1024 + tb] = l0;
                        g.Clo[bb + (long long)(c + 1) * 1024 + tb] = l1;
                    } else {
                        *(uint32_t*)(chi + c) = pk(h0, h1);
                        *(uint32_t*)(clo + c) = pk(l0, l1);
                    }
                }
            }
        }
}

__global__ void cvt_split_k(const float* __restrict__ x, bf16* __restrict__ hi, bf16* __restrict__ lo)
{
    int i = blockIdx.x * 256 + threadIdx.x;
    float4 v = ((const float4*)x)[i];
    bf16 h0=__float2bfloat16(v.x), h1=__float2bfloat16(v.y), h2=__float2bfloat16(v.z), h3=__float2bfloat16(v.w);
    bf16 l0=__float2bfloat16(v.x-__bfloat162float(h0)), l1=__float2bfloat16(v.y-__bfloat162float(h1));
    bf16 l2=__float2bfloat16(v.z-__bfloat162float(h2)), l3=__float2bfloat16(v.w-__bfloat162float(h3));
    ((uint2*)hi)[i] = make_uint2(pk(h0,h1), pk(h2,h3));
    ((uint2*)lo)[i] = make_uint2(pk(l0,l1), pk(l2,l3));
}

__global__ void softmax_split_k(const float* __restrict__ S, bf16* __restrict__ Ph, bf16* __restrict__ Pl)
{
    __shared__ float red[256];
    const float* p = S + (size_t)blockIdx.x * 1024;
    int tid = threadIdx.x;
    float4 v = ((const float4*)p)[tid];
    float m = fmaxf(fmaxf(v.x, v.y), fmaxf(v.z, v.w));
    red[tid] = m; __syncthreads();
    for (int s = 128; s > 0; s >>= 1) { if (tid < s) red[tid] = fmaxf(red[tid], red[tid+s]); __syncthreads(); }
    m = red[0]; __syncthreads();
    v.x = __expf(v.x-m); v.y = __expf(v.y-m); v.z = __expf(v.z-m); v.w = __expf(v.w-m);
    red[tid] = v.x+v.y+v.z+v.w; __syncthreads();
    for (int t = 128; t > 0; t >>= 1) { if (tid < t) red[tid] += red[tid+t]; __syncthreads(); }
    float inv = 1.f / red[0];
    v.x *= inv; v.y *= inv; v.z *= inv; v.w *= inv;
    bf16 h0=__float2bfloat16(v.x), h1=__float2bfloat16(v.y), h2=__float2bfloat16(v.z), h3=__float2bfloat16(v.w);
    bf16 l0=__float2bfloat16(v.x-__bfloat162float(h0)), l1=__float2bfloat16(v.y-__bfloat162float(h1));
    bf16 l2=__float2bfloat16(v.z-__bfloat162float(h2)), l3=__float2bfloat16(v.w-__bfloat162float(h3));
    size_t o = (size_t)blockIdx.x * 256 + tid;
    ((uint2*)Ph)[o] = make_uint2(pk(h0,h1), pk(h2,h3));
    ((uint2*)Pl)[o] = make_uint2(pk(l0,l1), pk(l2,l3));
}

extern "C" void kernel_launch(void* const* d_in, const int* in_sizes, int n_in,
                              void* d_out, int out_size)
{
    const float* f[3]  = { (const float*)d_in[0], (const float*)d_in[1], (const float*)d_in[2] };
    const float* W[12]; for (int j = 0; j < 12; j++) W[j] = (const float*)d_in[3 + j];
    const float* bp[3] = { (const float*)d_in[15], (const float*)d_in[16], (const float*)d_in[17] };
    float* out = (float*)d_out;

    bf16* BF = nullptr;  cudaGetSymbolAddress((void**)&BF, g_bf);
    float* S = nullptr;  cudaGetSymbolAddress((void**)&S, g_S);

    bf16 *FIN = BF, *FP = BF+OFF_FP, *Q = BF+OFF_Q, *Kp = BF+OFF_K, *VT = BF+OFF_VT, *Wb = BF+OFF_W;
    bf16 *Ph = BF+OFF_P, *Pl = BF+OFF_P+BIG;
#define PH_(b,i) ((b) + 2ULL*(i)*BIG)
#define PL_(b,i) ((b) + (2ULL*(i)+1)*BIG)
#define WH_(j) (Wb + 2ULL*(j)*MB1)
#define WL_(j) (Wb + (2ULL*(j)+1)*MB1)

    cudaFuncSetAttribute(gemm_mma<true, true, true, false>, cudaFuncAttributeMaxDynamicSharedMemorySize, SMEM_ALLOC);
    cudaFuncSetAttribute(gemm_mma<false,false,true, false>, cudaFuncAttributeMaxDynamicSharedMemorySize, SMEM_ALLOC);
    cudaFuncSetAttribute(gemm_mma<false,false,true, true >, cudaFuncAttributeMaxDynamicSharedMemorySize, SMEM_ALLOC);
    cudaFuncSetAttribute(gemm_mma<false,true, false,false>, cudaFuncAttributeMaxDynamicSharedMemorySize, SMEM_ALLOC);

    for (int i = 0; i < 3; i++)
        cvt_split_k<<<8192, 256>>>(f[i], PH_(FIN,i), PL_(FIN,i));
    for (int j = 0; j < 12; j++)
        cvt_split_k<<<1024, 256>>>(W[j], WH_(j), WL_(j));

    dim3 blk(256), gProj(8, 64, 1), gAttn(8, 8, 8);
    GArgs a = {};
    a.npairs = 1; a.sA = 0; a.sB = 0;

    // preprocess: fp_i = relu(f_i Wp_i^T + b_i) -> out[:, 3072+1024i) + split planes
    for (int i = 0; i < 3; i++) {
        a.Ah[0]=PH_(FIN,i); a.Al[0]=PL_(FIN,i); a.Bh[0]=WH_(i); a.Bl[0]=WL_(i);
        a.bias = bp[i]; a.Cf = out + 3072 + i*1024; a.ldcf = 6144; a.sCf = 0;
        a.Chi = PH_(FP,i); a.Clo = PL_(FP,i);
        gemm_mma<true, true, true, false><<<gProj, blk, SMEM_ALLOC>>>(a);
    }
    // QKV projections (V written transposed per batch)
    a.bias = nullptr; a.Cf = nullptr;
    for (int i = 0; i < 3; i++) {
        a.Ah[0]=PH_(FP,i); a.Al[0]=PL_(FP,i);
        a.Bh[0]=WH_(3+3*i); a.Bl[0]=WL_(3+3*i); a.Chi=PH_(Q,i);  a.Clo=PL_(Q,i);
        gemm_mma<false,false,true,false><<<gProj, blk, SMEM_ALLOC>>>(a);
        a.Bh[0]=WH_(4+3*i); a.Bl[0]=WL_(4+3*i); a.Chi=PH_(Kp,i); a.Clo=PL_(Kp,i);
        gemm_mma<false,false,true,false><<<gProj, blk, SMEM_ALLOC>>>(a);
        a.Bh[0]=WH_(5+3*i); a.Bl[0]=WL_(5+3*i); a.Chi=PH_(VT,i); a.Clo=PL_(VT,i);
        gemm_mma<false,false,true,true ><<<gProj, blk, SMEM_ALLOC>>>(a);
    }

    const int qidx[3][2] = { {1,2}, {0,2}, {0,1} };
    const int kidx[3][2] = { {0,0}, {2,1}, {2,2} };
    for (int mmod = 0; mmod < 3; mmod++) {
        GArgs s = {};
        s.npairs = 2; s.sA = 1048576; s.sB = 1048576;
        for (int p = 0; p < 2; p++) {
            s.Ah[p]=PH_(Q,qidx[mmod][p]);  s.Al[p]=PL_(Q,qidx[mmod][p]);
            s.Bh[p]=PH_(Kp,kidx[mmod][p]); s.Bl[p]=PL_(Kp,kidx[mmod][p]);
        }
        s.Cf = S; s.ldcf = 1024; s.sCf = 1048576;
        gemm_mma<false,true,false,false><<<gAttn, blk, SMEM_ALLOC>>>(s);

        softmax_split_k<<<8192, 256>>>(S, Ph, Pl);

        GArgs v = {};
        v.npairs = 1; v.sA = 1048576; v.sB = 1048576;
        v.Ah[0]=Ph; v.Al[0]=Pl; v.Bh[0]=PH_(VT,mmod); v.Bl[0]=PL_(VT,mmod);
        v.Cf = out + mmod*1024; v.ldcf = 6144; v.sCf = (long long)1024*6144;
        gemm_mma<false,true,false,false><<<gAttn, blk, SMEM_ALLOC>>>(v);
    }
}

// round 5
// speedup vs baseline: 3.5950x; 1.2854x over previous
#include <cuda_runtime.h>
#include <cuda_bf16.h>
#include <cstdint>

typedef __nv_bfloat16 bf16;

#define STAGES 3
#define STAGE_BYTES 32768               // A 128x128B + B 128x128B
#define SMEM_ALLOC (1024 + STAGES*STAGE_BYTES)

#define BIG 8388608ULL
#define MB1 1048576ULL

// bf16 arena: FIN 0-6, FP 6-12, Q 12-18, K 18-24, VT 24-30, QS1 30-32, P 32-38, W 38..+24MB1
__device__ bf16  g_bf[38ULL*BIG + 24ULL*MB1];
// f32 arena: S 0-3, T 3-4, Qf2 4-5, Qf3 5-6
__device__ float g_f[6ULL*BIG];

__device__ __forceinline__ uint32_t su32(const void* p){ return (uint32_t)__cvta_generic_to_shared(p); }
__device__ __forceinline__ void cp16(uint32_t s, const void* g){
    asm volatile("cp.async.cg.shared.global [%0], [%1], 16;"
        :: "r"(s), "l"((unsigned long long)__cvta_generic_to_global(g)) : "memory");
}
__device__ __forceinline__ uint32_t pk(bf16 a, bf16 b){
    return (uint32_t)__bfloat16_as_ushort(a) | ((uint32_t)__bfloat16_as_ushort(b) << 16);
}
__device__ __forceinline__ uint32_t swz(uint32_t o){ return o ^ ((o >> 3) & 0x70); }

__device__ __forceinline__ void ldsm4(uint32_t* r, uint32_t addr){
    asm volatile("ldmatrix.sync.aligned.m8n8.x4.shared.b16 {%0,%1,%2,%3}, [%4];"
        : "=r"(r[0]), "=r"(r[1]), "=r"(r[2]), "=r"(r[3]) : "r"(addr));
}
__device__ __forceinline__ void mma16816(float* d, const uint32_t* a, const uint32_t* b){
    asm volatile("mma.sync.aligned.m16n8k16.row.col.f32.bf16.bf16.f32 "
        "{%0,%1,%2,%3}, {%4,%5,%6,%7}, {%8,%9}, {%0,%1,%2,%3};"
        : "+f"(d[0]), "+f"(d[1]), "+f"(d[2]), "+f"(d[3])
        : "r"(a[0]), "r"(a[1]), "r"(a[2]), "r"(a[3]), "r"(b[0]), "r"(b[1]));
}

struct GDesc {
    const bf16 *Ah, *Al, *Bh, *Bl;
    long long sA, sB;
    const float* bias;
    const float* AccC; long long sAcc;
    float* Cf; long long sCf; int ldcf;
    bf16 *Chi, *Clo;
    int trans, relu, wf32, wsplit;
};
struct GTable { GDesc d[9]; int nb; };

__device__ __forceinline__ void ldfr(uint32_t (*afb)[4], uint32_t (*bfb)[4],
    uint32_t sa, uint32_t sb, int kb, int wm, int wn, int r8, int sg)
{
#pragma unroll
    for (int mt = 0; mt < 2; mt++) {
        int row = wm + mt*16 + r8 + ((sg & 1) << 3);
        ldsm4(afb[mt], sa + swz((uint32_t)(row*128 + kb + ((sg >> 1) << 4))));
    }
#pragma unroll
    for (int nq = 0; nq < 4; nq++) {
        int row = wn + nq*16 + r8 + ((sg >> 1) << 3);
        ldsm4(bfb[nq], sb + swz((uint32_t)(row*128 + kb + ((sg & 1) << 4))));
    }
}

// batched 3-term split GEMM: C = Ah Bh^T + Al Bh^T + Ah Bl^T (+AccC) (+bias,relu)
__global__ void __launch_bounds__(256) gemm_b(GTable t)
{
    extern __shared__ char smem[];
    const uint32_t tbase = (su32(smem) + 1023u) & ~1023u;
    const int tid = threadIdx.x, wid = tid >> 5, lane = tid & 31;
    const int di = blockIdx.z / t.nb, zb = blockIdx.z - di * t.nb;
    const GDesc g = t.d[di];
    const int m0 = blockIdx.y * 128, n0 = blockIdx.x * 128;
    const int wm = (wid & 3) * 32, wn = (wid >> 2) * 64;
    const int r8 = lane & 7, sg = lane >> 3;

    const bf16* Ah = g.Ah + (long long)zb * g.sA;
    const bf16* Al = g.Al + (long long)zb * g.sA;
    const bf16* Bh = g.Bh + (long long)zb * g.sB;
    const bf16* Bl = g.Bl + (long long)zb * g.sB;
    const bf16* sgA[3] = { Ah, Al, Ah };
    const bf16* sgB[3] = { Bh, Bh, Bl };

    float acc[2][8][4];
#pragma unroll
    for (int a = 0; a < 2; a++)
#pragma unroll
        for (int b = 0; b < 8; b++)
#pragma unroll
            for (int c = 0; c < 4; c++) acc[a][b][c] = 0.f;

    auto load_chunk = [&](int j) {
        const int seg = j >> 4, k0 = (j & 15) * 64, slot = j % 3;
        const bf16* Ap = sgA[seg];
        const bf16* Bp = sgB[seg];
        const uint32_t sa = tbase + slot * STAGE_BYTES, sb = sa + 16384;
#pragma unroll
        for (int u = 0; u < 4; u++) {
            int s = tid + 256 * u, row = s >> 3, cs = s & 7;
            uint32_t so = swz((uint32_t)(row * 128 + cs * 16));
            cp16(sa + so, Ap + (size_t)(m0 + row) * 1024 + k0 + cs * 8);
            cp16(sb + so, Bp + (size_t)(n0 + row) * 1024 + k0 + cs * 8);
        }
        asm volatile("cp.async.commit_group;" ::: "memory");
    };

    load_chunk(0);
    load_chunk(1);

    uint32_t af[2][2][4], bfr[2][4][4];

    for (int i = 0; i < 48; i++) {
        if (i == 47) asm volatile("cp.async.wait_group 0;" ::: "memory");
        else         asm volatile("cp.async.wait_group 1;" ::: "memory");
        __syncthreads();
        if (i + 2 < 48) load_chunk(i + 2);

        const uint32_t sa = tbase + (i % 3) * STAGE_BYTES, sb = sa + 16384;
        ldfr(af[0], bfr[0], sa, sb, 0, wm, wn, r8, sg);
#pragma unroll
        for (int ks = 0; ks < 4; ks++) {
            const int cur = ks & 1;
            if (ks < 3) ldfr(af[cur ^ 1], bfr[cur ^ 1], sa, sb, (ks + 1) * 32, wm, wn, r8, sg);
#pragma unroll
            for (int mt = 0; mt < 2; mt++)
#pragma unroll
                for (int nq = 0; nq < 4; nq++) {
                    mma16816(acc[mt][2*nq],     af[cur][mt], bfr[cur][nq]);
                    mma16816(acc[mt][2*nq + 1], af[cur][mt], bfr[cur][nq] + 2);
                }
        }
    }

#pragma unroll
    for (int mt = 0; mt < 2; mt++)
#pragma unroll
        for (int ri = 0; ri < 2; ri++) {
            const long long rg = m0 + wm + mt * 16 + ri * 8 + (lane >> 2);
            const float* accp = g.AccC ? g.AccC + (long long)zb * g.sAcc + rg * 1024 : nullptr;
            float* cf = g.wf32 ? g.Cf + (long long)zb * g.sCf + rg * (long long)g.ldcf : nullptr;
            bf16 *chi = nullptr, *clo = nullptr;
            long long bb = 0, tb = 0;
            if (g.wsplit) {
                if (g.trans) { bb = (rg >> 10) * 1048576LL; tb = rg & 1023LL; }
                else         { chi = g.Chi + rg * 1024LL; clo = g.Clo + rg * 1024LL; }
            }
#pragma unroll
            for (int nt = 0; nt < 8; nt++) {
                const int c = n0 + wn + nt * 8 + (lane & 3) * 2;
                float v0 = acc[mt][nt][ri * 2];
                float v1 = acc[mt][nt][ri * 2 + 1];
                if (accp) { float2 tv = *(const float2*)(accp + c); v0 += tv.x; v1 += tv.y; }
                if (g.relu) {
                    v0 = fmaxf(v0 + g.bias[c], 0.f);
                    v1 = fmaxf(v1 + g.bias[c + 1], 0.f);
                }
                if (cf) *(float2*)(cf + c) = make_float2(v0, v1);
                if (g.wsplit) {
                    bf16 h0 = __float2bfloat16(v0), h1 = __float2bfloat16(v1);
                    bf16 l0 = __float2bfloat16(v0 - __bfloat162float(h0));
                    bf16 l1 = __float2bfloat16(v1 - __bfloat162float(h1));
                    if (g.trans) {
                        g.Chi[bb + (long long)c * 1024 + tb] = h0;
                        g.Chi[bb + (long long)(c + 1) * 1024 + tb] = h1;
                        g.Clo[bb + (long long)c * 1024 + tb] = l0;
                        g.Clo[bb + (long long)(c + 1) * 1024 + tb] = l1;
                    } else {
                        *(uint32_t*)(chi + c) = pk(h0, h1);
                        *(uint32_t*)(clo + c) = pk(l0, l1);
                    }
                }
            }
        }
}

__device__ __forceinline__ void split4(float4 v, uint2& h, uint2& l)
{
    bf16 h0=__float2bfloat16(v.x), h1=__float2bfloat16(v.y), h2=__float2bfloat16(v.z), h3=__float2bfloat16(v.w);
    bf16 l0=__float2bfloat16(v.x-__bfloat162float(h0)), l1=__float2bfloat16(v.y-__bfloat162float(h1));
    bf16 l2=__float2bfloat16(v.z-__bfloat162float(h2)), l3=__float2bfloat16(v.w-__bfloat162float(h3));
    h = make_uint2(pk(h0,h1), pk(h2,h3));
    l = make_uint2(pk(l0,l1), pk(l2,l3));
}

// inputs: z = tensor index 0..2, dst planes at BF + 2z*BIG / (2z+1)*BIG
__global__ void cvt_in_k(const float* f0, const float* f1, const float* f2, bf16* base)
{
    const float* src = (blockIdx.y == 0) ? f0 : (blockIdx.y == 1) ? f1 : f2;
    size_t i = (size_t)blockIdx.x * 256 + threadIdx.x;
    uint2 h, l;
    split4(((const float4*)src)[i], h, l);
    ((uint2*)(base + 2ULL*blockIdx.y*BIG))[i] = h;
    ((uint2*)(base + (2ULL*blockIdx.y + 1)*BIG))[i] = l;
}

struct WPtrs { const float* p[12]; };
__global__ void cvt_w_k(WPtrs w, bf16* wb)
{
    size_t i = (size_t)blockIdx.x * 256 + threadIdx.x;
    uint2 h, l;
    split4(((const float4*)w.p[blockIdx.y])[i], h, l);
    ((uint2*)(wb + 2ULL*blockIdx.y*MB1))[i] = h;
    ((uint2*)(wb + (2ULL*blockIdx.y + 1)*MB1))[i] = l;
}

__global__ void add_split_k(const float* __restrict__ a, const float* __restrict__ b,
                            bf16* __restrict__ hi, bf16* __restrict__ lo)
{
    size_t i = (size_t)blockIdx.x * 256 + threadIdx.x;
    float4 x = ((const float4*)a)[i];
    float4 y = ((const float4*)b)[i];
    x.x += y.x; x.y += y.y; x.z += y.z; x.w += y.w;
    uint2 h, l;
    split4(x, h, l);
    ((uint2*)hi)[i] = h;
    ((uint2*)lo)[i] = l;
}

// softmax over rows of 1024; grid.x = 3*8192; modality = blockIdx.x >> 13
__global__ void softmax3_k(const float* __restrict__ S, bf16* __restrict__ P)
{
    __shared__ float red[256];
    const int m = blockIdx.x >> 13;
    const size_t row = blockIdx.x & 8191;
    const float* p = S + (size_t)m * BIG + row * 1024;
    int tid = threadIdx.x;
    float4 v = ((const float4*)p)[tid];
    float mx = fmaxf(fmaxf(v.x, v.y), fmaxf(v.z, v.w));
    red[tid] = mx; __syncthreads();
    for (int s = 128; s > 0; s >>= 1) { if (tid < s) red[tid] = fmaxf(red[tid], red[tid+s]); __syncthreads(); }
    mx = red[0]; __syncthreads();
    v.x = __expf(v.x-mx); v.y = __expf(v.y-mx); v.z = __expf(v.z-mx); v.w = __expf(v.w-mx);
    red[tid] = v.x + v.y + v.z + v.w; __syncthreads();
    for (int s = 128; s > 0; s >>= 1) { if (tid < s) red[tid] += red[tid+s]; __syncthreads(); }
    float inv = 1.f / red[0];
    v.x *= inv; v.y *= inv; v.z *= inv; v.w *= inv;
    uint2 h, l;
    split4(v, h, l);
    size_t o = row * 256 + tid;
    ((uint2*)(P + 2ULL*m*BIG))[o] = h;
    ((uint2*)(P + (2ULL*m + 1)*BIG))[o] = l;
}

extern "C" void kernel_launch(void* const* d_in, const int* in_sizes, int n_in,
                              void* d_out, int out_size)
{
    const float* f[3]  = { (const float*)d_in[0], (const float*)d_in[1], (const float*)d_in[2] };
    const float* W[12]; for (int j = 0; j < 12; j++) W[j] = (const float*)d_in[3 + j];
    const float* bp[3] = { (const float*)d_in[15], (const float*)d_in[16], (const float*)d_in[17] };
    float* out = (float*)d_out;

    bf16* BF = nullptr;  cudaGetSymbolAddress((void**)&BF, g_bf);
    float* F32 = nullptr; cudaGetSymbolAddress((void**)&F32, g_f);

    bf16 *FIN = BF, *FP = BF + 6*BIG, *Q = BF + 12*BIG, *Kb = BF + 18*BIG, *VT = BF + 24*BIG;
    bf16 *QS1h = BF + 30*BIG, *QS1l = BF + 31*BIG, *P = BF + 32*BIG, *Wb = BF + 38*BIG;
    float *S = F32, *T = F32 + 3*BIG, *Qf2 = F32 + 4*BIG, *Qf3 = F32 + 5*BIG;
#define PH_(b,i) ((b) + 2ULL*(i)*BIG)
#define PL_(b,i) ((b) + (2ULL*(i)+1)*BIG)
#define WH_(j) (Wb + 2ULL*(j)*MB1)
#define WL_(j) (Wb + (2ULL*(j)+1)*MB1)

    cudaFuncSetAttribute(gemm_b, cudaFuncAttributeMaxDynamicSharedMemorySize, SMEM_ALLOC);

    cvt_in_k<<<dim3(8192,3), 256>>>(f[0], f[1], f[2], BF);
    WPtrs wp; for (int j = 0; j < 12; j++) wp.p[j] = W[j];
    cvt_w_k<<<dim3(1024,12), 256>>>(wp, Wb);

    // 1) preprocess: fp_i = relu(f_i Wp_i^T + b_i) -> out + split
    {
        GTable t = {}; t.nb = 1;
        for (int i = 0; i < 3; i++) {
            GDesc& d = t.d[i];
            d.Ah = PH_(FIN,i); d.Al = PL_(FIN,i); d.Bh = WH_(i); d.Bl = WL_(i);
            d.bias = bp[i]; d.relu = 1;
            d.wf32 = 1; d.Cf = out + 3072 + i*1024; d.ldcf = 6144; d.sCf = 0;
            d.wsplit = 1; d.Chi = PH_(FP,i); d.Clo = PL_(FP,i);
        }
        gemm_b<<<dim3(8,64,3), 256, SMEM_ALLOC>>>(t);
    }
    // 2) QKV projections; Q2/Q3 also fp32; V transposed
    {
        GTable t = {}; t.nb = 1;
        for (int i = 0; i < 3; i++) {
            GDesc* d = &t.d[3*i];
            d[0].Ah = d[1].Ah = d[2].Ah = PH_(FP,i);
            d[0].Al = d[1].Al = d[2].Al = PL_(FP,i);
            d[0].Bh = WH_(3+3*i); d[0].Bl = WL_(3+3*i);
            d[1].Bh = WH_(4+3*i); d[1].Bl = WL_(4+3*i);
            d[2].Bh = WH_(5+3*i); d[2].Bl = WL_(5+3*i);
            d[0].wsplit = 1; d[0].Chi = PH_(Q,i);  d[0].Clo = PL_(Q,i);
            d[1].wsplit = 1; d[1].Chi = PH_(Kb,i); d[1].Clo = PL_(Kb,i);
            d[2].wsplit = 1; d[2].Chi = PH_(VT,i); d[2].Clo = PL_(VT,i); d[2].trans = 1;
            if (i == 1) { d[0].wf32 = 1; d[0].Cf = Qf2; d[0].ldcf = 1024; }
            if (i == 2) { d[0].wf32 = 1; d[0].Cf = Qf3; d[0].ldcf = 1024; }
        }
        gemm_b<<<dim3(8,64,9), 256, SMEM_ALLOC>>>(t);
    }
    // 3) qs1 = q2 + q3 (fp32) -> split
    add_split_k<<<8192, 256>>>(Qf2, Qf3, QS1h, QS1l);

    // 4) T = q1 . k3^T (fp32)
    {
        GTable t = {}; t.nb = 8;
        GDesc& d = t.d[0];
        d.Ah = PH_(Q,0); d.Al = PL_(Q,0); d.Bh = PH_(Kb,2); d.Bl = PL_(Kb,2);
        d.sA = 1048576; d.sB = 1048576;
        d.wf32 = 1; d.Cf = T; d.ldcf = 1024; d.sCf = 1048576;
        gemm_b<<<dim3(8,8,8), 256, SMEM_ALLOC>>>(t);
    }
    // 5) scores: s1 = qs1.k1 ; s2 = T + q3.k2 ; s3 = T + q2.k3
    {
        GTable t = {}; t.nb = 8;
        const bf16* ah[3] = { QS1h, PH_(Q,2), PH_(Q,1) };
        const bf16* al[3] = { QS1l, PL_(Q,2), PL_(Q,1) };
        const int ki[3] = { 0, 1, 2 };
        for (int m = 0; m < 3; m++) {
            GDesc& d = t.d[m];
            d.Ah = ah[m]; d.Al = al[m]; d.Bh = PH_(Kb,ki[m]); d.Bl = PL_(Kb,ki[m]);
            d.sA = 1048576; d.sB = 1048576;
            if (m > 0) { d.AccC = T; d.sAcc = 1048576; }
            d.wf32 = 1; d.Cf = S + (size_t)m*BIG; d.ldcf = 1024; d.sCf = 1048576;
        }
        gemm_b<<<dim3(8,8,24), 256, SMEM_ALLOC>>>(t);
    }
    // 6) softmax + split P for all 3 modalities
    softmax3_k<<<24576, 256>>>(S, P);

    // 7) AV: f_mu = P_m @ V_m -> out cols [m*1024, (m+1)*1024)
    {
        GTable t = {}; t.nb = 8;
        for (int m = 0; m < 3; m++) {
            GDesc& d = t.d[m];
            d.Ah = PH_(P,m); d.Al = PL_(P,m); d.Bh = PH_(VT,m); d.Bl = PL_(VT,m);
            d.sA = 1048576; d.sB = 1048576;
            d.wf32 = 1; d.Cf = out + m*1024; d.ldcf = 6144; d.sCf = (long long)1024*6144;
        }
        gemm_b<<<dim3(8,8,24), 256, SMEM_ALLOC>>>(t);
    }
}

// round 7
// speedup vs baseline: 3.6783x; 1.0232x over previous
#include <cuda_runtime.h>
#include <cuda_bf16.h>
#include <cstdint>

typedef __nv_bfloat16 bf16;

#define STAGES 3
#define STAGE_BYTES 32768               // A 128x128B + B 128x128B
#define SMEM_ALLOC (1024 + STAGES*STAGE_BYTES)

#define BIG 8388608ULL
#define MB1 1048576ULL

// bf16 arena: FIN 0-6, FP 6-12, Q 12-18, K 18-24, VT 24-30, QS1 30-32, P 32-38, W 38..+24MB1
__device__ bf16  g_bf[38ULL*BIG + 24ULL*MB1];
// f32 arena: S 0-3, T 3-4, Qf2 4-5, Qf3 5-6
__device__ float g_f[6ULL*BIG];

__device__ __forceinline__ uint32_t su32(const void* p){ return (uint32_t)__cvta_generic_to_shared(p); }
__device__ __forceinline__ void cp16(uint32_t s, const void* g){
    asm volatile("cp.async.cg.shared.global [%0], [%1], 16;"
        :: "r"(s), "l"((unsigned long long)__cvta_generic_to_global(g)) : "memory");
}
__device__ __forceinline__ uint32_t pk(bf16 a, bf16 b){
    return (uint32_t)__bfloat16_as_ushort(a) | ((uint32_t)__bfloat16_as_ushort(b) << 16);
}
__device__ __forceinline__ uint32_t swz(uint32_t o){ return o ^ ((o >> 3) & 0x70); }

__device__ __forceinline__ void ldsm4(uint32_t* r, uint32_t addr){
    asm volatile("ldmatrix.sync.aligned.m8n8.x4.shared.b16 {%0,%1,%2,%3}, [%4];"
        : "=r"(r[0]), "=r"(r[1]), "=r"(r[2]), "=r"(r[3]) : "r"(addr));
}
__device__ __forceinline__ void mma16816(float* d, const uint32_t* a, const uint32_t* b){
    asm volatile("mma.sync.aligned.m16n8k16.row.col.f32.bf16.bf16.f32 "
        "{%0,%1,%2,%3}, {%4,%5,%6,%7}, {%8,%9}, {%0,%1,%2,%3};"
        : "+f"(d[0]), "+f"(d[1]), "+f"(d[2]), "+f"(d[3])
        : "r"(a[0]), "r"(a[1]), "r"(a[2]), "r"(a[3]), "r"(b[0]), "r"(b[1]));
}

struct GDesc {
    const bf16 *Ah, *Al, *Bh, *Bl;
    long long sA, sB;
    const float* bias;
    const float* AccC; long long sAcc;
    float* Cf; long long sCf; int ldcf;
    bf16 *Chi, *Clo;
    int trans, relu, wf32, wsplit;
};
struct GTable { GDesc d[9]; int nb; };

// load one k-step of fragments for 64x64 warp tile
__device__ __forceinline__ void ldfr(uint32_t (*afb)[4], uint32_t (*bfb)[4],
    uint32_t sa, uint32_t sb, int kb, int wm, int wn, int r8, int sg)
{
#pragma unroll
    for (int mt = 0; mt < 4; mt++) {
        int row = wm + mt*16 + r8 + ((sg & 1) << 3);
        ldsm4(afb[mt], sa + swz((uint32_t)(row*128 + kb + ((sg >> 1) << 4))));
    }
#pragma unroll
    for (int nq = 0; nq < 4; nq++) {
        int row = wn + nq*16 + r8 + ((sg >> 1) << 3);
        ldsm4(bfb[nq], sb + swz((uint32_t)(row*128 + kb + ((sg & 1) << 4))));
    }
}

// batched 3-term split GEMM: C = Ah Bh^T + Al Bh^T + Ah Bl^T (+AccC) (+bias,relu)
// 128 threads, 4 warps, warp tile 64x64
__global__ void __launch_bounds__(128) gemm_b(GTable t)
{
    extern __shared__ char smem[];
    const uint32_t tbase = (su32(smem) + 1023u) & ~1023u;
    const int tid = threadIdx.x, wid = tid >> 5, lane = tid & 31;
    const int di = blockIdx.z / t.nb, zb = blockIdx.z - di * t.nb;
    const GDesc g = t.d[di];
    const int m0 = blockIdx.y * 128, n0 = blockIdx.x * 128;
    const int wm = (wid & 1) * 64, wn = (wid >> 1) * 64;
    const int r8 = lane & 7, sg = lane >> 3;

    const bf16* Ah = g.Ah + (long long)zb * g.sA;
    const bf16* Al = g.Al + (long long)zb * g.sA;
    const bf16* Bh = g.Bh + (long long)zb * g.sB;
    const bf16* Bl = g.Bl + (long long)zb * g.sB;
    const bf16* sgA[3] = { Ah, Al, Ah };
    const bf16* sgB[3] = { Bh, Bh, Bl };

    float acc[4][8][4];
#pragma unroll
    for (int a = 0; a < 4; a++)
#pragma unroll
        for (int b = 0; b < 8; b++)
#pragma unroll
            for (int c = 0; c < 4; c++) acc[a][b][c] = 0.f;

    auto load_chunk = [&](int j) {
        const int seg = j >> 4, k0 = (j & 15) * 64, slot = j % 3;
        const bf16* Ap = sgA[seg];
        const bf16* Bp = sgB[seg];
        const uint32_t sa = tbase + slot * STAGE_BYTES, sb = sa + 16384;
#pragma unroll
        for (int u = 0; u < 8; u++) {
            int s = tid + 128 * u, row = s >> 3, cs = s & 7;
            uint32_t so = swz((uint32_t)(row * 128 + cs * 16));
            cp16(sa + so, Ap + (size_t)(m0 + row) * 1024 + k0 + cs * 8);
            cp16(sb + so, Bp + (size_t)(n0 + row) * 1024 + k0 + cs * 8);
        }
        asm volatile("cp.async.commit_group;" ::: "memory");
    };

    load_chunk(0);
    load_chunk(1);

    uint32_t af[2][4][4], bfr[2][4][4];

    for (int i = 0; i < 48; i++) {
        if (i == 47) asm volatile("cp.async.wait_group 0;" ::: "memory");
        else         asm volatile("cp.async.wait_group 1;" ::: "memory");
        __syncthreads();
        if (i + 2 < 48) load_chunk(i + 2);

        const uint32_t sa = tbase + (i % 3) * STAGE_BYTES, sb = sa + 16384;
        ldfr(af[0], bfr[0], sa, sb, 0, wm, wn, r8, sg);
#pragma unroll
        for (int ks = 0; ks < 4; ks++) {
            const int cur = ks & 1;
            if (ks < 3) ldfr(af[cur ^ 1], bfr[cur ^ 1], sa, sb, (ks + 1) * 32, wm, wn, r8, sg);
#pragma unroll
            for (int mt = 0; mt < 4; mt++)
#pragma unroll
                for (int nq = 0; nq < 4; nq++) {
                    mma16816(acc[mt][2*nq],     af[cur][mt], bfr[cur][nq]);
                    mma16816(acc[mt][2*nq + 1], af[cur][mt], bfr[cur][nq] + 2);
                }
        }
    }

#pragma unroll
    for (int mt = 0; mt < 4; mt++)
#pragma unroll
        for (int ri = 0; ri < 2; ri++) {
            const long long rg = m0 + wm + mt * 16 + ri * 8 + (lane >> 2);
            const float* accp = g.AccC ? g.AccC + (long long)zb * g.sAcc + rg * 1024 : nullptr;
            float* cf = g.wf32 ? g.Cf + (long long)zb * g.sCf + rg * (long long)g.ldcf : nullptr;
            bf16 *chi = nullptr, *clo = nullptr;
            long long bb = 0, tb = 0;
            if (g.wsplit) {
                if (g.trans) { bb = (rg >> 10) * 1048576LL; tb = rg & 1023LL; }
                else         { chi = g.Chi + rg * 1024LL; clo = g.Clo + rg * 1024LL; }
            }
#pragma unroll
            for (int nt = 0; nt < 8; nt++) {
                const int c = n0 + wn + nt * 8 + (lane & 3) * 2;
                float v0 = acc[mt][nt][ri * 2];
                float v1 = acc[mt][nt][ri * 2 + 1];
                if (accp) { float2 tv = *(const float2*)(accp + c); v0 += tv.x; v1 += tv.y; }
                if (g.relu) {
                    v0 = fmaxf(v0 + g.bias[c], 0.f);
                    v1 = fmaxf(v1 + g.bias[c + 1], 0.f);
                }
                if (cf) *(float2*)(cf + c) = make_float2(v0, v1);
                if (g.wsplit) {
                    bf16 h0 = __float2bfloat16(v0), h1 = __float2bfloat16(v1);
                    bf16 l0 = __float2bfloat16(v0 - __bfloat162float(h0));
                    bf16 l1 = __float2bfloat16(v1 - __bfloat162float(h1));
                    if (g.trans) {
                        g.Chi[bb + (long long)c * 1024 + tb] = h0;
                        g.Chi[bb + (long long)(c + 1) * 1024 + tb] = h1;
                        g.Clo[bb + (long long)c * 1024 + tb] = l0;
                        g.Clo[bb + (long long)(c + 1) * 1024 + tb] = l1;
                    } else {
                        *(uint32_t*)(chi + c) = pk(h0, h1);
                        *(uint32_t*)(clo + c) = pk(l0, l1);
                    }
                }
            }
        }
}

__device__ __forceinline__ void split4(float4 v, uint2& h, uint2& l)
{
    bf16 h0=__float2bfloat16(v.x), h1=__float2bfloat16(v.y), h2=__float2bfloat16(v.z), h3=__float2bfloat16(v.w);
    bf16 l0=__float2bfloat16(v.x-__bfloat162float(h0)), l1=__float2bfloat16(v.y-__bfloat162float(h1));
    bf16 l2=__float2bfloat16(v.z-__bfloat162float(h2)), l3=__float2bfloat16(v.w-__bfloat162float(h3));
    h = make_uint2(pk(h0,h1), pk(h2,h3));
    l = make_uint2(pk(l0,l1), pk(l2,l3));
}

__global__ void cvt_in_k(const float* f0, const float* f1, const float* f2, bf16* base)
{
    const float* src = (blockIdx.y == 0) ? f0 : (blockIdx.y == 1) ? f1 : f2;
    size_t i = (size_t)blockIdx.x * 256 + threadIdx.x;
    uint2 h, l;
    split4(((const float4*)src)[i], h, l);
    ((uint2*)(base + 2ULL*blockIdx.y*BIG))[i] = h;
    ((uint2*)(base + (2ULL*blockIdx.y + 1)*BIG))[i] = l;
}

struct WPtrs { const float* p[12]; };
__global__ void cvt_w_k(WPtrs w, bf16* wb)
{
    size_t i = (size_t)blockIdx.x * 256 + threadIdx.x;
    uint2 h, l;
    split4(((const float4*)w.p[blockIdx.y])[i], h, l);
    ((uint2*)(wb + 2ULL*blockIdx.y*MB1))[i] = h;
    ((uint2*)(wb + (2ULL*blockIdx.y + 1)*MB1))[i] = l;
}

__global__ void add_split_k(const float* __restrict__ a, const float* __restrict__ b,
                            bf16* __restrict__ hi, bf16* __restrict__ lo)
{
    size_t i = (size_t)blockIdx.x * 256 + threadIdx.x;
    float4 x = ((const float4*)a)[i];
    float4 y = ((const float4*)b)[i];
    x.x += y.x; x.y += y.y; x.z += y.z; x.w += y.w;
    uint2 h, l;
    split4(x, h, l);
    ((uint2*)hi)[i] = h;
    ((uint2*)lo)[i] = l;
}

// softmax over rows of 1024; grid.x = 3*8192; modality = blockIdx.x >> 13
__global__ void softmax3_k(const float* __restrict__ S, bf16* __restrict__ P)
{
    __shared__ float red[256];
    const int m = blockIdx.x >> 13;
    const size_t row = blockIdx.x & 8191;
    const float* p = S + (size_t)m * BIG + row * 1024;
    int tid = threadIdx.x;
    float4 v = ((const float4*)p)[tid];
    float mx = fmaxf(fmaxf(v.x, v.y), fmaxf(v.z, v.w));
    red[tid] = mx; __syncthreads();
    for (int s = 128; s > 0; s >>= 1) { if (tid < s) red[tid] = fmaxf(red[tid], red[tid+s]); __syncthreads(); }
    mx = red[0]; __syncthreads();
    v.x = __expf(v.x-mx); v.y = __expf(v.y-mx); v.z = __expf(v.z-mx); v.w = __expf(v.w-mx);
    red[tid] = v.x + v.y + v.z + v.w; __syncthreads();
    for (int s = 128; s > 0; s >>= 1) { if (tid < s) red[tid] += red[tid+s]; __syncthreads(); }
    float inv = 1.f / red[0];
    v.x *= inv; v.y *= inv; v.z *= inv; v.w *= inv;
    uint2 h, l;
    split4(v, h, l);
    size_t o = row * 256 + tid;
    ((uint2*)(P + 2ULL*m*BIG))[o] = h;
    ((uint2*)(P + (2ULL*m + 1)*BIG))[o] = l;
}

extern "C" void kernel_launch(void* const* d_in, const int* in_sizes, int n_in,
                              void* d_out, int out_size)
{
    const float* f[3]  = { (const float*)d_in[0], (const float*)d_in[1], (const float*)d_in[2] };
    const float* W[12]; for (int j = 0; j < 12; j++) W[j] = (const float*)d_in[3 + j];
    const float* bp[3] = { (const float*)d_in[15], (const float*)d_in[16], (const float*)d_in[17] };
    float* out = (float*)d_out;

    bf16* BF = nullptr;  cudaGetSymbolAddress((void**)&BF, g_bf);
    float* F32 = nullptr; cudaGetSymbolAddress((void**)&F32, g_f);

    bf16 *FIN = BF, *FP = BF + 6*BIG, *Q = BF + 12*BIG, *Kb = BF + 18*BIG, *VT = BF + 24*BIG;
    bf16 *QS1h = BF + 30*BIG, *QS1l = BF + 31*BIG, *P = BF + 32*BIG, *Wb = BF + 38*BIG;
    float *S = F32, *T = F32 + 3*BIG, *Qf2 = F32 + 4*BIG, *Qf3 = F32 + 5*BIG;
#define PH_(b,i) ((b) + 2ULL*(i)*BIG)
#define PL_(b,i) ((b) + (2ULL*(i)+1)*BIG)
#define WH_(j) (Wb + 2ULL*(j)*MB1)
#define WL_(j) (Wb + (2ULL*(j)+1)*MB1)

    cudaFuncSetAttribute(gemm_b, cudaFuncAttributeMaxDynamicSharedMemorySize, SMEM_ALLOC);

    cvt_in_k<<<dim3(8192,3), 256>>>(f[0], f[1], f[2], BF);
    WPtrs wp; for (int j = 0; j < 12; j++) wp.p[j] = W[j];
    cvt_w_k<<<dim3(1024,12), 256>>>(wp, Wb);

    // 1) preprocess: fp_i = relu(f_i Wp_i^T + b_i) -> out + split
    {
        GTable t = {}; t.nb = 1;
        for (int i = 0; i < 3; i++) {
            GDesc& d = t.d[i];
            d.Ah = PH_(FIN,i); d.Al = PL_(FIN,i); d.Bh = WH_(i); d.Bl = WL_(i);
            d.bias = bp[i]; d.relu = 1;
            d.wf32 = 1; d.Cf = out + 3072 + i*1024; d.ldcf = 6144; d.sCf = 0;
            d.wsplit = 1; d.Chi = PH_(FP,i); d.Clo = PL_(FP,i);
        }
        gemm_b<<<dim3(8,64,3), 128, SMEM_ALLOC>>>(t);
    }
    // 2) QKV projections; Q2/Q3 also fp32; V transposed
    {
        GTable t = {}; t.nb = 1;
        for (int i = 0; i < 3; i++) {
            GDesc* d = &t.d[3*i];
            d[0].Ah = d[1].Ah = d[2].Ah = PH_(FP,i);
            d[0].Al = d[1].Al = d[2].Al = PL_(FP,i);
            d[0].Bh = WH_(3+3*i); d[0].Bl = WL_(3+3*i);
            d[1].Bh = WH_(4+3*i); d[1].Bl = WL_(4+3*i);
            d[2].Bh = WH_(5+3*i); d[2].Bl = WL_(5+3*i);
            d[0].wsplit = 1; d[0].Chi = PH_(Q,i);  d[0].Clo = PL_(Q,i);
            d[1].wsplit = 1; d[1].Chi = PH_(Kb,i); d[1].Clo = PL_(Kb,i);
            d[2].wsplit = 1; d[2].Chi = PH_(VT,i); d[2].Clo = PL_(VT,i); d[2].trans = 1;
            if (i == 1) { d[0].wf32 = 1; d[0].Cf = Qf2; d[0].ldcf = 1024; }
            if (i == 2) { d[0].wf32 = 1; d[0].Cf = Qf3; d[0].ldcf = 1024; }
        }
        gemm_b<<<dim3(8,64,9), 128, SMEM_ALLOC>>>(t);
    }
    // 3) qs1 = q2 + q3 (fp32) -> split
    add_split_k<<<8192, 256>>>(Qf2, Qf3, QS1h, QS1l);

    // 4) T = q1 . k3^T (fp32)
    {
        GTable t = {}; t.nb = 8;
        GDesc& d = t.d[0];
        d.Ah = PH_(Q,0); d.Al = PL_(Q,0); d.Bh = PH_(Kb,2); d.Bl = PL_(Kb,2);
        d.sA = 1048576; d.sB = 1048576;
        d.wf32 = 1; d.Cf = T; d.ldcf = 1024; d.sCf = 1048576;
        gemm_b<<<dim3(8,8,8), 128, SMEM_ALLOC>>>(t);
    }
    // 5) scores: s1 = qs1.k1 ; s2 = T + q3.k2 ; s3 = T + q2.k3
    {
        GTable t = {}; t.nb = 8;
        const bf16* ah[3] = { QS1h, PH_(Q,2), PH_(Q,1) };
        const bf16* al[3] = { QS1l, PL_(Q,2), PL_(Q,1) };
        const int ki[3] = { 0, 1, 2 };
        for (int m = 0; m < 3; m++) {
            GDesc& d = t.d[m];
            d.Ah = ah[m]; d.Al = al[m]; d.Bh = PH_(Kb,ki[m]); d.Bl = PL_(Kb,ki[m]);
            d.sA = 1048576; d.sB = 1048576;
            if (m > 0) { d.AccC = T; d.sAcc = 1048576; }
            d.wf32 = 1; d.Cf = S + (size_t)m*BIG; d.ldcf = 1024; d.sCf = 1048576;
        }
        gemm_b<<<dim3(8,8,24), 128, SMEM_ALLOC>>>(t);
    }
    // 6) softmax + split P for all 3 modalities
    softmax3_k<<<24576, 256>>>(S, P);

    // 7) AV: f_mu = P_m @ V_m -> out cols [m*1024, (m+1)*1024)
    {
        GTable t = {}; t.nb = 8;
        for (int m = 0; m < 3; m++) {
            GDesc& d = t.d[m];
            d.Ah = PH_(P,m); d.Al = PL_(P,m); d.Bh = PH_(VT,m); d.Bl = PL_(VT,m);
            d.sA = 1048576; d.sB = 1048576;
            d.wf32 = 1; d.Cf = out + m*1024; d.ldcf = 6144; d.sCf = (long long)1024*6144;
        }
        gemm_b<<<dim3(8,8,24), 128, SMEM_ALLOC>>>(t);
    }
}